// round 7
// baseline (speedup 1.0000x reference)
#include <cuda_runtime.h>

// Shapes (fixed by the reference setup_inputs):
//   predicted_noise [32, 4, 512, 512] f32   (d_in[0])
//   target_noise    [32, 4, 512, 512] f32   (d_in[1])
//   text_tokens     [32, 64] int64          (d_in[2], UNUSED by the math)
//   text_positions  [32, 64, 2] f32         (d_in[3])
// Output: 1 x f32 scalar.
//
// result = mean over (b,c,h,w) of (1 + 3*mask[b,h,w]) * (p - t)^2
// (WEIGHT = 1.0 collapses base_loss out of the expression).
//
// R5: R3 structure (32-reg streaming loop, SMEM mask slice) with 8-row
// tiles -> 2048 CTAs so SMs reach full 8-CTA residency (R3's 1024 CTAs
// left SMs at 6.92/8 => occ 81%, DRAM 73%).

#define NB 32
#define NC 4
#define NH 512
#define NW 512
#define NT 64
#define BOX 5

#define ROWS_PER_BLOCK 8
#define CHUNKS_PER_BATCH (NH / ROWS_PER_BLOCK)     // 64
#define GRID (NB * CHUNKS_PER_BATCH)               // 2048
#define THREADS 256
#define N_ELEMS (NB * NC * NH * NW)                // 33554432
#define F4_PER_ROW (NW / 4)                        // 128
#define TILE_F4 (NC * ROWS_PER_BLOCK * F4_PER_ROW) // 4096 float4 per block
#define ITERS (TILE_F4 / THREADS)                  // 16

__device__ float    g_partials[GRID];
__device__ unsigned g_count = 0;   // wraps to 0 via atomicInc each replay

__global__ void __launch_bounds__(THREADS)
fused_loss_kernel(const float4* __restrict__ p,
                  const float4* __restrict__ q,
                  const float*  __restrict__ pos,
                  float* __restrict__ out) {
    __shared__ unsigned smask[ROWS_PER_BLOCK][NW / 32];   // 8 x 16 words
    __shared__ float    ssum[THREADS / 32];
    __shared__ bool     s_last;

    const int tid   = threadIdx.x;
    const int batch = blockIdx.x >> 6;          // / CHUNKS_PER_BATCH
    const int chunk = blockIdx.x & 63;
    const int h0    = chunk * ROWS_PER_BLOCK;

    // ---- build mask slice for rows [h0, h0+8) in SMEM ----
    if (tid < ROWS_PER_BLOCK * (NW / 32))
        ((unsigned*)smask)[tid] = 0u;
    __syncthreads();
    if (tid < NT) {
        float x = pos[(batch * NT + tid) * 2 + 0];
        float y = pos[(batch * NT + tid) * 2 + 1];
        if (x > 0.0f && y > 0.0f) {
            int xp = (int)floorf(x * (float)NW);
            int yp = (int)floorf(y * (float)NH);
            int x0 = max(xp - BOX, 0);
            int x1 = min(xp + BOX, NW);
            int y0 = max(max(yp - BOX, 0), h0);
            int y1 = min(min(yp + BOX, NH), h0 + ROWS_PER_BLOCK);
            if (x0 < x1 && y0 < y1) {
                int w0 = x0 >> 5;
                int w1 = (x1 - 1) >> 5;
                unsigned m0, m1 = 0u;
                if (w0 == w1) {
                    m0 = ((1u << (x1 - x0)) - 1u) << (x0 & 31);   // width <= 10 < 32
                } else {
                    m0 = ~0u << (x0 & 31);
                    m1 = (1u << (x1 - (w1 << 5))) - 1u;           // 1..9 bits
                }
                for (int i = y0; i < y1; i++) {
                    atomicOr(&smask[i - h0][w0], m0);
                    if (w0 != w1) atomicOr(&smask[i - h0][w1], m1);
                }
            }
        }
    }
    __syncthreads();

    // ---- stream this block's 128 KB (4 channels x 8 rows x 512 cols x 2) ----
    const int base_img = batch * NC;
    float sum = 0.0f;
    #pragma unroll 4
    for (int k = 0; k < ITERS; k++) {
        int idx = tid + k * THREADS;          // 0..4095
        int ch  = idx >> 10;                  // / (8*128)
        int rem = idx & 1023;
        int row = rem >> 7;                   // 0..7
        int c4  = rem & 127;                  // float4 column
        int g = ((base_img + ch) << 16) + ((h0 + row) << 7) + c4;

        float4 a = p[g];
        float4 b = q[g];
        unsigned bits = smask[row][c4 >> 3] >> ((c4 & 7) << 2);

        float d0 = a.x - b.x; d0 *= d0;
        float d1 = a.y - b.y; d1 *= d1;
        float d2 = a.z - b.z; d2 *= d2;
        float d3 = a.w - b.w; d3 *= d3;

        float m = (float)(bits & 1u)        * d0
                + (float)((bits >> 1) & 1u) * d1
                + (float)((bits >> 2) & 1u) * d2
                + (float)((bits >> 3) & 1u) * d3;
        sum += (d0 + d1 + d2 + d3) + 3.0f * m;
    }

    // ---- block reduce ----
    #pragma unroll
    for (int o = 16; o > 0; o >>= 1)
        sum += __shfl_xor_sync(0xFFFFFFFFu, sum, o);
    int lane = tid & 31, wid = tid >> 5;
    if (lane == 0) ssum[wid] = sum;
    __syncthreads();
    if (wid == 0) {
        float v = (lane < THREADS / 32) ? ssum[lane] : 0.0f;
        #pragma unroll
        for (int o = 4; o > 0; o >>= 1)
            v += __shfl_xor_sync(0xFFFFFFFFu, v, o);
        if (lane == 0) {
            g_partials[blockIdx.x] = v;
            __threadfence();
            unsigned prev = atomicInc(&g_count, GRID - 1);  // wraps to 0 after last
            s_last = (prev == GRID - 1);
        }
    }
    __syncthreads();

    // ---- last block folds partials, writes scalar ----
    if (s_last) {
        double d = 0.0;
        for (int i = tid; i < GRID; i += THREADS)
            d += (double)g_partials[i];
        #pragma unroll
        for (int o = 16; o > 0; o >>= 1)
            d += __shfl_xor_sync(0xFFFFFFFFu, d, o);
        __shared__ double dsum[THREADS / 32];
        if (lane == 0) dsum[wid] = d;
        __syncthreads();
        if (wid == 0) {
            double t = (lane < THREADS / 32) ? dsum[lane] : 0.0;
            #pragma unroll
            for (int o = 4; o > 0; o >>= 1)
                t += __shfl_xor_sync(0xFFFFFFFFu, t, o);
            if (lane == 0)
                out[0] = (float)(t * (1.0 / (double)N_ELEMS));
        }
    }
}

extern "C" void kernel_launch(void* const* d_in, const int* in_sizes, int n_in,
                              void* d_out, int out_size) {
    const float* pred = (const float*)d_in[0];
    const float* targ = (const float*)d_in[1];
    // d_in[2] (text_tokens) is unused by the math.
    const float* pos  = (const float*)d_in[3];
    fused_loss_kernel<<<GRID, THREADS>>>((const float4*)pred,
                                         (const float4*)targ,
                                         pos, (float*)d_out);
}

// round 11
// speedup vs baseline: 1.0377x; 1.0377x over previous
#include <cuda_runtime.h>

// Shapes (fixed by the reference setup_inputs):
//   predicted_noise [32, 4, 512, 512] f32   (d_in[0])
//   target_noise    [32, 4, 512, 512] f32   (d_in[1])
//   text_tokens     [32, 64] int64          (d_in[2], UNUSED by the math)
//   text_positions  [32, 64, 2] f32         (d_in[3])
// Output: 1 x f32 scalar.
//
// result = mean over (b,c,h,w) of (1 + 3*mask[b,h,w]) * (p - t)^2
// (WEIGHT = 1.0 collapses base_loss out of the expression).
//
// R6: decouple mask from streaming.
//   paint:  1 thread per (batch,row) builds 16 mask words in regs, writes
//           coalesced (no zeroing, no atomics). ~2-3us.
//   reduce: flat grid-stride, GRID = 148*8 = 1184 so every CTA is resident
//           in wave 1 with perfect balance (R3's tile-coupled grid capped
//           SM fill at 86%). R3's proven 32-reg loop body; mask word is an
//           L2-hit LDG.32 shared by 8 float4s. Last block finalizes.

#define NB 32
#define NC 4
#define NH 512
#define NW 512
#define NT 64
#define BOX 5

#define WORDS_PER_ROW   (NW / 32)                 // 16
#define WORDS_PER_BATCH (NH * WORDS_PER_ROW)      // 8192 = 2^13
#define MASK_WORDS      (NB * WORDS_PER_BATCH)    // 262144 (1 MB)
#define N_ELEMS         (NB * NC * NH * NW)       // 33554432 = 2^25
#define N4              (N_ELEMS / 4)             // 8388608

#define RGRID    1184                              // 148 SMs * 8 CTAs
#define RTHREADS 256

__device__ unsigned g_mask[MASK_WORDS];
__device__ float    g_partials[RGRID];
__device__ unsigned g_count = 0;   // wraps to 0 via atomicInc each replay

// ---------------------------------------------------------------------------
// paint: one thread per (batch, row). Build the row's 16 words in registers
// from the 64 tokens (cached in smem), write coalesced. Overwrites fully, so
// no zeroing pass and replays stay deterministic.
// ---------------------------------------------------------------------------
__global__ void __launch_bounds__(256)
paint_kernel(const float* __restrict__ pos) {
    __shared__ float sx[NT], sy[NT];
    const int tid   = threadIdx.x;
    const int batch = blockIdx.x >> 1;            // 2 blocks per batch
    const int row   = ((blockIdx.x & 1) << 8) + tid;

    if (tid < NT * 2) {
        float v = pos[(batch * NT) * 2 + tid];
        if (tid & 1) sy[tid >> 1] = v; else sx[tid >> 1] = v;
    }
    __syncthreads();

    unsigned w[WORDS_PER_ROW];
    #pragma unroll
    for (int k = 0; k < WORDS_PER_ROW; k++) w[k] = 0u;

    for (int t = 0; t < NT; t++) {
        float x = sx[t], y = sy[t];
        if (!(x > 0.0f && y > 0.0f)) continue;
        int yp = (int)floorf(y * (float)NH);
        if (row < yp - BOX || row >= yp + BOX) continue;
        int xp = (int)floorf(x * (float)NW);
        int x0 = max(xp - BOX, 0);
        int x1 = min(xp + BOX, NW);
        if (x0 >= x1) continue;
        int w0 = x0 >> 5;
        int w1 = (x1 - 1) >> 5;
        if (w0 == w1) {
            w[w0] |= ((1u << (x1 - x0)) - 1u) << (x0 & 31);   // width <= 10 < 32
        } else {
            w[w0] |= ~0u << (x0 & 31);
            w[w1] |= (1u << (x1 - (w1 << 5))) - 1u;           // 1..9 bits
        }
    }

    uint4* dst = (uint4*)&g_mask[batch * WORDS_PER_BATCH + row * WORDS_PER_ROW];
    #pragma unroll
    for (int k = 0; k < 4; k++)
        dst[k] = make_uint4(w[4 * k], w[4 * k + 1], w[4 * k + 2], w[4 * k + 3]);
}

// ---------------------------------------------------------------------------
// reduce: flat grid-stride over N4 float4 pairs. All index math is shifts:
//   fi = i*4; batch = fi >> 20; spatial = fi & (2^18 - 1).
// Mask word: g_mask[(batch<<13) + (spatial>>5)], L2-resident (1 MB).
// ---------------------------------------------------------------------------
__global__ void __launch_bounds__(RTHREADS)
reduce_kernel(const float4* __restrict__ p,
              const float4* __restrict__ q,
              float* __restrict__ out) {
    float sum = 0.0f;
    const int stride = RGRID * RTHREADS;
    #pragma unroll 4
    for (int i = blockIdx.x * RTHREADS + threadIdx.x; i < N4; i += stride) {
        float4 a = p[i];
        float4 b = q[i];
        unsigned fi = (unsigned)i << 2;
        unsigned bidx = fi >> 20;
        unsigned spatial = fi & ((1u << 18) - 1u);
        unsigned bits = g_mask[(bidx << 13) + (spatial >> 5)] >> (spatial & 31u);

        float d0 = a.x - b.x; d0 *= d0;
        float d1 = a.y - b.y; d1 *= d1;
        float d2 = a.z - b.z; d2 *= d2;
        float d3 = a.w - b.w; d3 *= d3;

        float m = (float)(bits & 1u)        * d0
                + (float)((bits >> 1) & 1u) * d1
                + (float)((bits >> 2) & 1u) * d2
                + (float)((bits >> 3) & 1u) * d3;
        sum += (d0 + d1 + d2 + d3) + 3.0f * m;
    }

    // block reduce
    #pragma unroll
    for (int o = 16; o > 0; o >>= 1)
        sum += __shfl_xor_sync(0xFFFFFFFFu, sum, o);
    __shared__ float ssum[RTHREADS / 32];
    __shared__ bool  s_last;
    int lane = threadIdx.x & 31, wid = threadIdx.x >> 5;
    if (lane == 0) ssum[wid] = sum;
    __syncthreads();
    if (wid == 0) {
        float v = (lane < RTHREADS / 32) ? ssum[lane] : 0.0f;
        #pragma unroll
        for (int o = 4; o > 0; o >>= 1)
            v += __shfl_xor_sync(0xFFFFFFFFu, v, o);
        if (lane == 0) {
            g_partials[blockIdx.x] = v;
            __threadfence();
            unsigned prev = atomicInc(&g_count, RGRID - 1);  // wraps after last
            s_last = (prev == RGRID - 1);
        }
    }
    __syncthreads();

    // last block folds partials, writes scalar
    if (s_last) {
        double d = 0.0;
        for (int i = threadIdx.x; i < RGRID; i += RTHREADS)
            d += (double)g_partials[i];
        #pragma unroll
        for (int o = 16; o > 0; o >>= 1)
            d += __shfl_xor_sync(0xFFFFFFFFu, d, o);
        __shared__ double dsum[RTHREADS / 32];
        if (lane == 0) dsum[wid] = d;
        __syncthreads();
        if (wid == 0) {
            double t = (lane < RTHREADS / 32) ? dsum[lane] : 0.0;
            #pragma unroll
            for (int o = 4; o > 0; o >>= 1)
                t += __shfl_xor_sync(0xFFFFFFFFu, t, o);
            if (lane == 0)
                out[0] = (float)(t * (1.0 / (double)N_ELEMS));
        }
    }
}

extern "C" void kernel_launch(void* const* d_in, const int* in_sizes, int n_in,
                              void* d_out, int out_size) {
    const float* pred = (const float*)d_in[0];
    const float* targ = (const float*)d_in[1];
    // d_in[2] (text_tokens) is unused by the math.
    const float* pos  = (const float*)d_in[3];

    paint_kernel<<<NB * 2, 256>>>(pos);
    reduce_kernel<<<RGRID, RTHREADS>>>((const float4*)pred,
                                       (const float4*)targ,
                                       (float*)d_out);
}